// round 5
// baseline (speedup 1.0000x reference)
#include <cuda_runtime.h>

#define NNODES 50000
#define NEDGES 600000
#define DIM 128
#define NREL 3

// Scratch (device globals; no allocation allowed)
__device__ float g_agg[NNODES * DIM];     // 25.6 MB scatter accumulator
__device__ float g_deg[NNODES];
__device__ int   g_cnt[NREL];
__device__ int   g_perm[NREL * NEDGES];   // bucketed edge ids, one segment per relation
__device__ float g_linT[DIM * DIM];       // lin_w transposed: linT[k][j] = lin_w[j][k]

// ---------------------------------------------------------------------------
// Zero per-launch state (graph replays re-run this).
__global__ void zero_kernel() {
    int idx = blockIdx.x * blockDim.x + threadIdx.x;
    int stride = gridDim.x * blockDim.x;
    float4* a4 = (float4*)g_agg;
    const int n4 = NNODES * DIM / 4;
    for (int i = idx; i < n4; i += stride) a4[i] = make_float4(0.f, 0.f, 0.f, 0.f);
    for (int i = idx; i < NNODES; i += stride) g_deg[i] = 0.f;
    if (idx < NREL) g_cnt[idx] = 0;
}

// ---------------------------------------------------------------------------
// Transpose lin_w so the epilogue reads it coalesced.
__global__ void transpose_kernel(const float* __restrict__ lin_w) {
    int j = threadIdx.x;   // 0..127
    int k = blockIdx.x;    // 0..127
    g_linT[k * DIM + j] = lin_w[j * DIM + k];
}

// ---------------------------------------------------------------------------
// Bucket edges by relation; also compute degree. edge_index/edge_type are int32.
__global__ void bucket_kernel(const int* __restrict__ ei,
                              const int* __restrict__ et, int E) {
    __shared__ int scnt[NREL], sbase[NREL], scur[NREL];
    int start = blockIdx.x * 8192;
    int end = min(start + 8192, E);
    if (threadIdx.x < NREL) { scnt[threadIdx.x] = 0; scur[threadIdx.x] = 0; }
    __syncthreads();
    for (int i = start + threadIdx.x; i < end; i += blockDim.x) {
        int r = min(max(et[i], 0), NREL - 1);
        atomicAdd(&scnt[r], 1);
    }
    __syncthreads();
    if (threadIdx.x < NREL)
        sbase[threadIdx.x] = atomicAdd(&g_cnt[threadIdx.x], scnt[threadIdx.x]);
    __syncthreads();
    for (int i = start + threadIdx.x; i < end; i += blockDim.x) {
        int r = min(max(et[i], 0), NREL - 1);
        int slot = atomicAdd(&scur[r], 1);
        g_perm[r * NEDGES + sbase[r] + slot] = i;
        int dst = ei[E + i];
        atomicAdd(&g_deg[dst], 1.0f);
    }
}

// ---------------------------------------------------------------------------
// Edge GEMM: warp handles 8 edges of one relation.
// msg[e, j] = sum_k x[src_e, k] * W[r][k, j]; red.v4 into g_agg[dst_e].
__global__ void __launch_bounds__(256) edge_kernel(const float* __restrict__ x,
                                                   const int* __restrict__ ei,
                                                   const float* __restrict__ relw,
                                                   int E) {
    __shared__ float xs[8][8 * DIM];  // per-warp 8 gathered x rows
    int warp = threadIdx.x >> 5, lane = threadIdx.x & 31;
    int gw = blockIdx.x * 8 + warp;
    int nw = gridDim.x * 8;
    float* myxs = xs[warp];

    for (int r = 0; r < NREL; r++) {
        int c = g_cnt[r];
        int ng = (c + 7) >> 3;
        const float4* W4 = (const float4*)(relw + r * DIM * DIM);
        const int* perm = g_perm + r * NEDGES;
        for (int g = gw; g < ng; g += nw) {
            int e0 = g << 3;
            int nv = min(8, c - e0);
            int dsts[8];
            __syncwarp();
            #pragma unroll
            for (int i = 0; i < 8; i++) {
                int j = (i < nv) ? (e0 + i) : e0;   // pad with a valid edge
                int e = perm[j];
                int s = ei[e];
                dsts[i] = ei[E + e];
                float4 p = ((const float4*)x)[s * 32 + lane];
                ((float4*)(myxs + i * DIM))[lane] = p;
            }
            __syncwarp();

            float4 acc[8];
            #pragma unroll
            for (int i = 0; i < 8; i++) acc[i] = make_float4(0.f, 0.f, 0.f, 0.f);

            for (int k4 = 0; k4 < DIM / 4; k4++) {
                float4 xk[8];
                #pragma unroll
                for (int i = 0; i < 8; i++)
                    xk[i] = ((const float4*)(myxs + i * DIM))[k4];  // broadcast LDS.128
                #pragma unroll
                for (int kk = 0; kk < 4; kk++) {
                    float4 wv = W4[(k4 * 4 + kk) * 32 + lane];
                    #pragma unroll
                    for (int i = 0; i < 8; i++) {
                        float xv = (kk == 0) ? xk[i].x
                                 : (kk == 1) ? xk[i].y
                                 : (kk == 2) ? xk[i].z : xk[i].w;
                        acc[i].x = fmaf(xv, wv.x, acc[i].x);
                        acc[i].y = fmaf(xv, wv.y, acc[i].y);
                        acc[i].z = fmaf(xv, wv.z, acc[i].z);
                        acc[i].w = fmaf(xv, wv.w, acc[i].w);
                    }
                }
            }

            #pragma unroll
            for (int i = 0; i < 8; i++) {
                if (i < nv) {
                    float* p = g_agg + dsts[i] * DIM + lane * 4;
                    asm volatile("red.global.add.v4.f32 [%0], {%1,%2,%3,%4};"
                                 :: "l"(p), "f"(acc[i].x), "f"(acc[i].y),
                                    "f"(acc[i].z), "f"(acc[i].w)
                                 : "memory");
                }
            }
        }
    }
}

// ---------------------------------------------------------------------------
// Epilogue: h = x @ lin_w^T + lin_b + agg/deg; LayerNorm. Warp per node.
__global__ void __launch_bounds__(256) final_kernel(const float* __restrict__ x,
                                                    const float* __restrict__ lin_b,
                                                    const float* __restrict__ gamma,
                                                    const float* __restrict__ beta,
                                                    float* __restrict__ out, int N) {
    __shared__ float xs[8][DIM];
    int warp = threadIdx.x >> 5, lane = threadIdx.x & 31;
    int node = blockIdx.x * 8 + warp;
    if (node >= N) return;
    float4 p = ((const float4*)x)[node * 32 + lane];
    ((float4*)xs[warp])[lane] = p;
    __syncwarp();

    float4 acc = ((const float4*)lin_b)[lane];
    const float4* LT4 = (const float4*)g_linT;
    #pragma unroll 4
    for (int k = 0; k < DIM; k++) {
        float xv = xs[warp][k];
        float4 wv = LT4[k * 32 + lane];
        acc.x = fmaf(xv, wv.x, acc.x);
        acc.y = fmaf(xv, wv.y, acc.y);
        acc.z = fmaf(xv, wv.z, acc.z);
        acc.w = fmaf(xv, wv.w, acc.w);
    }

    float d = fmaxf(g_deg[node], 1.0f);
    float inv = 1.0f / d;
    float4 a = ((const float4*)g_agg)[node * 32 + lane];
    acc.x = fmaf(a.x, inv, acc.x);
    acc.y = fmaf(a.y, inv, acc.y);
    acc.z = fmaf(a.z, inv, acc.z);
    acc.w = fmaf(a.w, inv, acc.w);

    // LayerNorm
    float s = acc.x + acc.y + acc.z + acc.w;
    #pragma unroll
    for (int o = 16; o > 0; o >>= 1) s += __shfl_xor_sync(0xffffffffu, s, o);
    float mu = s * (1.0f / DIM);
    float4 t = make_float4(acc.x - mu, acc.y - mu, acc.z - mu, acc.w - mu);
    float q = t.x * t.x + t.y * t.y + t.z * t.z + t.w * t.w;
    #pragma unroll
    for (int o = 16; o > 0; o >>= 1) q += __shfl_xor_sync(0xffffffffu, q, o);
    float var = q * (1.0f / DIM);
    float rs = rsqrtf(var + 1e-5f);

    float4 gm = ((const float4*)gamma)[lane];
    float4 bt = ((const float4*)beta)[lane];
    float4 o4;
    o4.x = fmaf(gm.x * t.x, rs, bt.x);
    o4.y = fmaf(gm.y * t.y, rs, bt.y);
    o4.z = fmaf(gm.z * t.z, rs, bt.z);
    o4.w = fmaf(gm.w * t.w, rs, bt.w);
    ((float4*)out)[node * 32 + lane] = o4;
}

// ---------------------------------------------------------------------------
extern "C" void kernel_launch(void* const* d_in, const int* in_sizes, int n_in,
                              void* d_out, int out_size) {
    const float* x     = (const float*)d_in[0];
    const int*   ei    = (const int*)d_in[1];
    const int*   et    = (const int*)d_in[2];
    const float* relw  = (const float*)d_in[3];
    const float* lin_w = (const float*)d_in[4];
    const float* lin_b = (const float*)d_in[5];
    const float* gamma = (const float*)d_in[6];
    const float* beta  = (const float*)d_in[7];
    float* out = (float*)d_out;

    int N = in_sizes[0] / DIM;
    int E = in_sizes[2];

    zero_kernel<<<2048, 256>>>();
    transpose_kernel<<<DIM, DIM>>>(lin_w);
    bucket_kernel<<<(E + 8191) / 8192, 256>>>(ei, et, E);
    edge_kernel<<<1184, 256>>>(x, ei, relw, E);
    final_kernel<<<(N + 7) / 8, 256>>>(x, lin_b, gamma, beta, out, N);
}

// round 7
// speedup vs baseline: 1.6257x; 1.6257x over previous
#include <cuda_runtime.h>
#include <cstdint>

#define NNODES 50000
#define NEDGES 600000
#define DIM 128
#define NREL 3

// ---------------- device scratch (no allocations allowed) -------------------
__device__ float g_hsum[NREL * NNODES * DIM];   // per-relation x-row sums (76.8MB)
__device__ float g_deg[NNODES];
__device__ float g_linT[DIM * DIM];             // lin_w transposed

// ---------------------------------------------------------------------------
__global__ void zero_kernel() {
    int idx = blockIdx.x * blockDim.x + threadIdx.x;
    int stride = gridDim.x * blockDim.x;
    float4* h4 = (float4*)g_hsum;
    const int n4 = NREL * NNODES * DIM / 4;
    for (int i = idx; i < n4; i += stride) h4[i] = make_float4(0.f, 0.f, 0.f, 0.f);
    for (int i = idx; i < NNODES; i += stride) g_deg[i] = 0.f;
}

__global__ void transpose_kernel(const float* __restrict__ lin_w) {
    int j = threadIdx.x, k = blockIdx.x;
    g_linT[k * DIM + j] = lin_w[j * DIM + k];
}

// ---------------------------------------------------------------------------
// Scatter: for each edge, Hsum[r][dst] += x[src]; deg[dst] += 1.
// Warp handles 32 edges; inner loop 4-wide for MLP on the row gathers.
__global__ void __launch_bounds__(256) scatter_kernel(const float* __restrict__ x,
                                                      const int* __restrict__ ei,
                                                      const int* __restrict__ et,
                                                      int E) {
    int gw = (blockIdx.x * blockDim.x + threadIdx.x) >> 5;
    int lane = threadIdx.x & 31;
    int base = gw * 32;
    if (base >= E) return;
    int n = min(32, E - base);

    int s = 0, dr = 0;
    if (lane < n) {
        int idx = base + lane;
        s = ei[idx];
        int d = ei[E + idx];
        int r = min(max(et[idx], 0), NREL - 1);
        dr = (d << 2) | r;
        asm volatile("red.global.add.f32 [%0], %1;"
                     :: "l"(g_deg + d), "f"(1.0f) : "memory");
    }

    const float4* x4 = (const float4*)x;
    int i = 0;
    for (; i + 4 <= n; i += 4) {
        int s0 = __shfl_sync(0xffffffffu, s, i);
        int s1 = __shfl_sync(0xffffffffu, s, i + 1);
        int s2 = __shfl_sync(0xffffffffu, s, i + 2);
        int s3 = __shfl_sync(0xffffffffu, s, i + 3);
        int q0 = __shfl_sync(0xffffffffu, dr, i);
        int q1 = __shfl_sync(0xffffffffu, dr, i + 1);
        int q2 = __shfl_sync(0xffffffffu, dr, i + 2);
        int q3 = __shfl_sync(0xffffffffu, dr, i + 3);
        float4 p0 = x4[s0 * 32 + lane];
        float4 p1 = x4[s1 * 32 + lane];
        float4 p2 = x4[s2 * 32 + lane];
        float4 p3 = x4[s3 * 32 + lane];
        float* a0 = g_hsum + ((size_t)(q0 & 3) * NNODES + (q0 >> 2)) * DIM + lane * 4;
        float* a1 = g_hsum + ((size_t)(q1 & 3) * NNODES + (q1 >> 2)) * DIM + lane * 4;
        float* a2 = g_hsum + ((size_t)(q2 & 3) * NNODES + (q2 >> 2)) * DIM + lane * 4;
        float* a3 = g_hsum + ((size_t)(q3 & 3) * NNODES + (q3 >> 2)) * DIM + lane * 4;
        asm volatile("red.global.add.v4.f32 [%0], {%1,%2,%3,%4};"
                     :: "l"(a0), "f"(p0.x), "f"(p0.y), "f"(p0.z), "f"(p0.w) : "memory");
        asm volatile("red.global.add.v4.f32 [%0], {%1,%2,%3,%4};"
                     :: "l"(a1), "f"(p1.x), "f"(p1.y), "f"(p1.z), "f"(p1.w) : "memory");
        asm volatile("red.global.add.v4.f32 [%0], {%1,%2,%3,%4};"
                     :: "l"(a2), "f"(p2.x), "f"(p2.y), "f"(p2.z), "f"(p2.w) : "memory");
        asm volatile("red.global.add.v4.f32 [%0], {%1,%2,%3,%4};"
                     :: "l"(a3), "f"(p3.x), "f"(p3.y), "f"(p3.z), "f"(p3.w) : "memory");
    }
    for (; i < n; i++) {
        int si = __shfl_sync(0xffffffffu, s, i);
        int qi = __shfl_sync(0xffffffffu, dr, i);
        float4 p = x4[si * 32 + lane];
        float* a = g_hsum + ((size_t)(qi & 3) * NNODES + (qi >> 2)) * DIM + lane * 4;
        asm volatile("red.global.add.v4.f32 [%0], {%1,%2,%3,%4};"
                     :: "l"(a), "f"(p.x), "f"(p.y), "f"(p.z), "f"(p.w) : "memory");
    }
}

// ---------------------------------------------------------------------------
// Fused node GEMM + epilogue (packed f32x2 FMA):
// h = x@linT + b + (Σ_r Hsum_r[node] @ W_r)/deg; LayerNorm. Warp per node.
__global__ void __launch_bounds__(256) final_kernel(const float* __restrict__ x,
                                                    const float* __restrict__ relw,
                                                    const float* __restrict__ lin_b,
                                                    const float* __restrict__ gamma,
                                                    const float* __restrict__ beta,
                                                    float* __restrict__ out, int N) {
    __shared__ float xs[8][DIM];
    int warp = threadIdx.x >> 5, lane = threadIdx.x & 31;
    int node = blockIdx.x * 8 + warp;
    if (node >= N) return;

    ((float4*)xs[warp])[lane] = ((const float4*)x)[node * 32 + lane];
    __syncwarp();

    float4 b4 = ((const float4*)lin_b)[lane];
    unsigned long long a01, a23;
    asm("mov.b64 %0, {%1,%2};" : "=l"(a01) : "f"(b4.x), "f"(b4.y));
    asm("mov.b64 %0, {%1,%2};" : "=l"(a23) : "f"(b4.z), "f"(b4.w));

    const float4* xs4 = (const float4*)xs[warp];
    {
        const ulonglong2* W2 = (const ulonglong2*)g_linT;
        #pragma unroll 4
        for (int k4 = 0; k4 < 32; k4++) {
            float4 xk = xs4[k4];
            #pragma unroll
            for (int j = 0; j < 4; j++) {
                float xv = (j == 0) ? xk.x : (j == 1) ? xk.y : (j == 2) ? xk.z : xk.w;
                unsigned long long xv2;
                asm("mov.b64 %0, {%1,%1};" : "=l"(xv2) : "f"(xv));
                ulonglong2 w = W2[(k4 * 4 + j) * 32 + lane];
                asm("fma.rn.f32x2 %0, %1, %2, %0;" : "+l"(a01) : "l"(xv2), "l"(w.x));
                asm("fma.rn.f32x2 %0, %1, %2, %0;" : "+l"(a23) : "l"(xv2), "l"(w.y));
            }
        }
    }

    unsigned long long g01 = 0ull, g23 = 0ull;  // {0.f,0.f}
    for (int r = 0; r < NREL; r++) {
        __syncwarp();
        ((float4*)xs[warp])[lane] =
            ((const float4*)(g_hsum + ((size_t)r * NNODES + node) * DIM))[lane];
        __syncwarp();
        const ulonglong2* W2 = (const ulonglong2*)(relw + r * DIM * DIM);
        #pragma unroll 4
        for (int k4 = 0; k4 < 32; k4++) {
            float4 xk = xs4[k4];
            #pragma unroll
            for (int j = 0; j < 4; j++) {
                float xv = (j == 0) ? xk.x : (j == 1) ? xk.y : (j == 2) ? xk.z : xk.w;
                unsigned long long xv2;
                asm("mov.b64 %0, {%1,%1};" : "=l"(xv2) : "f"(xv));
                ulonglong2 w = W2[(k4 * 4 + j) * 32 + lane];
                asm("fma.rn.f32x2 %0, %1, %2, %0;" : "+l"(g01) : "l"(xv2), "l"(w.x));
                asm("fma.rn.f32x2 %0, %1, %2, %0;" : "+l"(g23) : "l"(xv2), "l"(w.y));
            }
        }
    }

    float ax, ay, az, aw, gx, gy, gz, gw;
    asm("mov.b64 {%0,%1}, %2;" : "=f"(ax), "=f"(ay) : "l"(a01));
    asm("mov.b64 {%0,%1}, %2;" : "=f"(az), "=f"(aw) : "l"(a23));
    asm("mov.b64 {%0,%1}, %2;" : "=f"(gx), "=f"(gy) : "l"(g01));
    asm("mov.b64 {%0,%1}, %2;" : "=f"(gz), "=f"(gw) : "l"(g23));

    float inv = 1.0f / fmaxf(g_deg[node], 1.0f);
    float4 acc;
    acc.x = fmaf(gx, inv, ax);
    acc.y = fmaf(gy, inv, ay);
    acc.z = fmaf(gz, inv, az);
    acc.w = fmaf(gw, inv, aw);

    // LayerNorm
    float s = acc.x + acc.y + acc.z + acc.w;
    #pragma unroll
    for (int o = 16; o > 0; o >>= 1) s += __shfl_xor_sync(0xffffffffu, s, o);
    float mu = s * (1.0f / DIM);
    float4 t = make_float4(acc.x - mu, acc.y - mu, acc.z - mu, acc.w - mu);
    float q = t.x * t.x + t.y * t.y + t.z * t.z + t.w * t.w;
    #pragma unroll
    for (int o = 16; o > 0; o >>= 1) q += __shfl_xor_sync(0xffffffffu, q, o);
    float rs = rsqrtf(q * (1.0f / DIM) + 1e-5f);

    float4 gm = ((const float4*)gamma)[lane];
    float4 bt = ((const float4*)beta)[lane];
    float4 o4;
    o4.x = fmaf(gm.x * t.x, rs, bt.x);
    o4.y = fmaf(gm.y * t.y, rs, bt.y);
    o4.z = fmaf(gm.z * t.z, rs, bt.z);
    o4.w = fmaf(gm.w * t.w, rs, bt.w);
    ((float4*)out)[node * 32 + lane] = o4;
}

// ---------------------------------------------------------------------------
extern "C" void kernel_launch(void* const* d_in, const int* in_sizes, int n_in,
                              void* d_out, int out_size) {
    const float* x     = (const float*)d_in[0];
    const int*   ei    = (const int*)d_in[1];
    const int*   et    = (const int*)d_in[2];
    const float* relw  = (const float*)d_in[3];
    const float* lin_w = (const float*)d_in[4];
    const float* lin_b = (const float*)d_in[5];
    const float* gamma = (const float*)d_in[6];
    const float* beta  = (const float*)d_in[7];
    float* out = (float*)d_out;

    int N = in_sizes[0] / DIM;
    int E = in_sizes[2];

    zero_kernel<<<2048, 256>>>();
    transpose_kernel<<<DIM, DIM>>>(lin_w);
    int warps = (E + 31) / 32;
    scatter_kernel<<<(warps + 7) / 8, 256>>>(x, ei, et, E);
    final_kernel<<<(N + 7) / 8, 256>>>(x, relw, lin_b, gamma, beta, out, N);
}

// round 10
// speedup vs baseline: 2.7554x; 1.6949x over previous
#include <cuda_runtime.h>
#include <cstdint>

#define NNODES 50000
#define NEDGES 600000
#define DIM 128
#define NREL 3

#define BM 128
#define BK 32
#define KTOT 512          // 128 (lin) + 3*128 (relations)
#define AS_STRIDE 133     // [BK][BM] stride, conflict-free scalar STS
#define WS_STRIDE 132     // [BK][128] stride (16B aligned rows)

// ---------------- device scratch (no allocations allowed) -------------------
__device__ float g_hsum[NREL * NNODES * DIM];   // per-relation x-row sums
__device__ float g_deg[NNODES];
__device__ float g_inv[NNODES];
__device__ float g_wcat[KTOT * DIM];            // [linT; W0; W1; W2], row-major [k][n]

// ---------------------------------------------------------------------------
__global__ void zero_kernel() {
    int idx = blockIdx.x * blockDim.x + threadIdx.x;
    int stride = gridDim.x * blockDim.x;
    float4* h4 = (float4*)g_hsum;
    const int n4 = NREL * NNODES * DIM / 4;
    for (int i = idx; i < n4; i += stride) h4[i] = make_float4(0.f, 0.f, 0.f, 0.f);
    for (int i = idx; i < NNODES; i += stride) g_deg[i] = 0.f;
}

// Wcat[k][n]: k<128 -> lin_w[n][k] (transposed); else relation r = (k-128)/128.
__global__ void build_wcat(const float* __restrict__ lin_w,
                           const float* __restrict__ relw) {
    int k = blockIdx.x, j = threadIdx.x;
    float v;
    if (k < DIM) v = lin_w[j * DIM + k];
    else {
        int r = (k - DIM) >> 7, kk = (k - DIM) & 127;
        v = relw[r * DIM * DIM + kk * DIM + j];
    }
    g_wcat[k * DIM + j] = v;
}

__global__ void inv_kernel() {
    int i = blockIdx.x * blockDim.x + threadIdx.x;
    if (i < NNODES) g_inv[i] = 1.0f / fmaxf(g_deg[i], 1.0f);
}

// ---------------------------------------------------------------------------
// Scatter: Hsum[r][dst] += x[src]; deg[dst] += 1. Warp per 32 edges, MLP=4.
__global__ void __launch_bounds__(256) scatter_kernel(const float* __restrict__ x,
                                                      const int* __restrict__ ei,
                                                      const int* __restrict__ et,
                                                      int E) {
    int gw = (blockIdx.x * blockDim.x + threadIdx.x) >> 5;
    int lane = threadIdx.x & 31;
    int base = gw * 32;
    if (base >= E) return;
    int n = min(32, E - base);

    int s = 0, dr = 0;
    if (lane < n) {
        int idx = base + lane;
        s = ei[idx];
        int d = ei[E + idx];
        int r = min(max(et[idx], 0), NREL - 1);
        dr = (d << 2) | r;
        asm volatile("red.global.add.f32 [%0], %1;"
                     :: "l"(g_deg + d), "f"(1.0f) : "memory");
    }

    const float4* x4 = (const float4*)x;
    int i = 0;
    for (; i + 4 <= n; i += 4) {
        int s0 = __shfl_sync(0xffffffffu, s, i);
        int s1 = __shfl_sync(0xffffffffu, s, i + 1);
        int s2 = __shfl_sync(0xffffffffu, s, i + 2);
        int s3 = __shfl_sync(0xffffffffu, s, i + 3);
        int q0 = __shfl_sync(0xffffffffu, dr, i);
        int q1 = __shfl_sync(0xffffffffu, dr, i + 1);
        int q2 = __shfl_sync(0xffffffffu, dr, i + 2);
        int q3 = __shfl_sync(0xffffffffu, dr, i + 3);
        float4 p0 = x4[s0 * 32 + lane];
        float4 p1 = x4[s1 * 32 + lane];
        float4 p2 = x4[s2 * 32 + lane];
        float4 p3 = x4[s3 * 32 + lane];
        float* a0 = g_hsum + ((size_t)(q0 & 3) * NNODES + (q0 >> 2)) * DIM + lane * 4;
        float* a1 = g_hsum + ((size_t)(q1 & 3) * NNODES + (q1 >> 2)) * DIM + lane * 4;
        float* a2 = g_hsum + ((size_t)(q2 & 3) * NNODES + (q2 >> 2)) * DIM + lane * 4;
        float* a3 = g_hsum + ((size_t)(q3 & 3) * NNODES + (q3 >> 2)) * DIM + lane * 4;
        asm volatile("red.global.add.v4.f32 [%0], {%1,%2,%3,%4};"
                     :: "l"(a0), "f"(p0.x), "f"(p0.y), "f"(p0.z), "f"(p0.w) : "memory");
        asm volatile("red.global.add.v4.f32 [%0], {%1,%2,%3,%4};"
                     :: "l"(a1), "f"(p1.x), "f"(p1.y), "f"(p1.z), "f"(p1.w) : "memory");
        asm volatile("red.global.add.v4.f32 [%0], {%1,%2,%3,%4};"
                     :: "l"(a2), "f"(p2.x), "f"(p2.y), "f"(p2.z), "f"(p2.w) : "memory");
        asm volatile("red.global.add.v4.f32 [%0], {%1,%2,%3,%4};"
                     :: "l"(a3), "f"(p3.x), "f"(p3.y), "f"(p3.z), "f"(p3.w) : "memory");
    }
    for (; i < n; i++) {
        int si = __shfl_sync(0xffffffffu, s, i);
        int qi = __shfl_sync(0xffffffffu, dr, i);
        float4 p = x4[si * 32 + lane];
        float* a = g_hsum + ((size_t)(qi & 3) * NNODES + (qi >> 2)) * DIM + lane * 4;
        asm volatile("red.global.add.v4.f32 [%0], {%1,%2,%3,%4};"
                     :: "l"(a), "f"(p.x), "f"(p.y), "f"(p.z), "f"(p.w) : "memory");
    }
}

// ---------------------------------------------------------------------------
// Fused GEMM + LayerNorm. C[128 nodes][128 out] per block, 8x8 per thread.
// A[node, k] = k<128 ? x[node,k] : Hsum[r][node,k%128] * inv_deg[node].
__global__ __launch_bounds__(256, 2) void final_gemm_kernel(
        const float* __restrict__ x,
        const float* __restrict__ lin_b,
        const float* __restrict__ gamma,
        const float* __restrict__ beta,
        float* __restrict__ out, int N) {
    __shared__ float As[BK * AS_STRIDE];   // [k][row]
    __shared__ float Ws[BK * WS_STRIDE];   // [k][col]

    int tid = threadIdx.x;
    int tx = tid & 15, ty = tid >> 4;      // col group, row group
    int node0 = blockIdx.x * BM;

    unsigned long long acc[8][4];
    #pragma unroll
    for (int m = 0; m < 8; m++)
        #pragma unroll
        for (int p = 0; p < 4; p++) acc[m][p] = 0ull;

    auto loadA = [&](int kc, float4* pa) {
        #pragma unroll
        for (int i = 0; i < 4; i++) {
            int idx = tid + 256 * i;
            int row = idx >> 3, kq = idx & 7;
            int node = node0 + row;
            float4 v = make_float4(0.f, 0.f, 0.f, 0.f);
            if (node < N) {
                int k = kc * BK + kq * 4;
                int seg = k >> 7, koff = k & 127;
                if (seg == 0) {
                    v = *(const float4*)(x + (size_t)node * DIM + koff);
                } else {
                    v = *(const float4*)(g_hsum +
                        ((size_t)(seg - 1) * NNODES + node) * DIM + koff);
                    float iv = g_inv[node];
                    v.x *= iv; v.y *= iv; v.z *= iv; v.w *= iv;
                }
            }
            pa[i] = v;
        }
    };
    auto loadW = [&](int kc, float4* pw) {
        #pragma unroll
        for (int i = 0; i < 4; i++) {
            int idx = tid + 256 * i;
            int kk = idx >> 5, q = idx & 31;
            pw[i] = *(const float4*)(g_wcat + (size_t)(kc * BK + kk) * DIM + q * 4);
        }
    };

    float4 pa[4], pw[4];
    loadA(0, pa);
    loadW(0, pw);

    for (int kc = 0; kc < KTOT / BK; kc++) {
        #pragma unroll
        for (int i = 0; i < 4; i++) {
            int idx = tid + 256 * i;
            int row = idx >> 3, kq = idx & 7;
            As[(kq * 4 + 0) * AS_STRIDE + row] = pa[i].x;
            As[(kq * 4 + 1) * AS_STRIDE + row] = pa[i].y;
            As[(kq * 4 + 2) * AS_STRIDE + row] = pa[i].z;
            As[(kq * 4 + 3) * AS_STRIDE + row] = pa[i].w;
            int kk = idx >> 5, q = idx & 31;
            *(float4*)&Ws[kk * WS_STRIDE + q * 4] = pw[i];
        }
        __syncthreads();
        if (kc + 1 < KTOT / BK) { loadA(kc + 1, pa); loadW(kc + 1, pw); }

        #pragma unroll 4
        for (int k = 0; k < BK; k++) {
            const float* ar = &As[k * AS_STRIDE + ty * 8];
            const float* wr = &Ws[k * WS_STRIDE + tx * 8];
            ulonglong2 wA = *(const ulonglong2*)wr;
            ulonglong2 wB = *(const ulonglong2*)(wr + 4);
            #pragma unroll
            for (int m = 0; m < 8; m++) {
                float a = ar[m];
                unsigned long long a2;
                asm("mov.b64 %0, {%1,%1};" : "=l"(a2) : "f"(a));
                asm("fma.rn.f32x2 %0, %1, %2, %0;" : "+l"(acc[m][0]) : "l"(a2), "l"(wA.x));
                asm("fma.rn.f32x2 %0, %1, %2, %0;" : "+l"(acc[m][1]) : "l"(a2), "l"(wA.y));
                asm("fma.rn.f32x2 %0, %1, %2, %0;" : "+l"(acc[m][2]) : "l"(a2), "l"(wB.x));
                asm("fma.rn.f32x2 %0, %1, %2, %0;" : "+l"(acc[m][3]) : "l"(a2), "l"(wB.y));
            }
        }
        __syncthreads();
    }

    // ---- fused LayerNorm epilogue on register accumulators ----
    float4 b0  = *(const float4*)(lin_b + tx * 8);
    float4 b1  = *(const float4*)(lin_b + tx * 8 + 4);
    float4 g0  = *(const float4*)(gamma + tx * 8);
    float4 g1  = *(const float4*)(gamma + tx * 8 + 4);
    float4 be0 = *(const float4*)(beta + tx * 8);
    float4 be1 = *(const float4*)(beta + tx * 8 + 4);

    #pragma unroll
    for (int m = 0; m < 8; m++) {
        int node = node0 + ty * 8 + m;
        float c[8];
        asm("mov.b64 {%0,%1}, %2;" : "=f"(c[0]), "=f"(c[1]) : "l"(acc[m][0]));
        asm("mov.b64 {%0,%1}, %2;" : "=f"(c[2]), "=f"(c[3]) : "l"(acc[m][1]));
        asm("mov.b64 {%0,%1}, %2;" : "=f"(c[4]), "=f"(c[5]) : "l"(acc[m][2]));
        asm("mov.b64 {%0,%1}, %2;" : "=f"(c[6]), "=f"(c[7]) : "l"(acc[m][3]));
        c[0] += b0.x; c[1] += b0.y; c[2] += b0.z; c[3] += b0.w;
        c[4] += b1.x; c[5] += b1.y; c[6] += b1.z; c[7] += b1.w;

        float s = 0.f, q = 0.f;
        #pragma unroll
        for (int j = 0; j < 8; j++) { s += c[j]; q += c[j] * c[j]; }
        // reduce across the 16 tx lanes (same half-warp)
        #pragma unroll
        for (int o = 8; o > 0; o >>= 1) {
            s += __shfl_xor_sync(0xffffffffu, s, o);
            q += __shfl_xor_sync(0xffffffffu, q, o);
        }
        float mu = s * (1.0f / DIM);
        float var = q * (1.0f / DIM) - mu * mu;
        float rs = rsqrtf(fmaxf(var, 0.f) + 1e-5f);

        if (node < N) {
            float4 o0, o1;
            o0.x = fmaf(g0.x * (c[0] - mu), rs, be0.x);
            o0.y = fmaf(g0.y * (c[1] - mu), rs, be0.y);
            o0.z = fmaf(g0.z * (c[2] - mu), rs, be0.z);
            o0.w = fmaf(g0.w * (c[3] - mu), rs, be0.w);
            o1.x = fmaf(g1.x * (c[4] - mu), rs, be1.x);
            o1.y = fmaf(g1.y * (c[5] - mu), rs, be1.y);
            o1.z = fmaf(g1.z * (c[6] - mu), rs, be1.z);
            o1.w = fmaf(g1.w * (c[7] - mu), rs, be1.w);
            *(float4*)(out + (size_t)node * DIM + tx * 8)     = o0;
            *(float4*)(out + (size_t)node * DIM + tx * 8 + 4) = o1;
        }
    }
}

// ---------------------------------------------------------------------------
extern "C" void kernel_launch(void* const* d_in, const int* in_sizes, int n_in,
                              void* d_out, int out_size) {
    const float* x     = (const float*)d_in[0];
    const int*   ei    = (const int*)d_in[1];
    const int*   et    = (const int*)d_in[2];
    const float* relw  = (const float*)d_in[3];
    const float* lin_w = (const float*)d_in[4];
    const float* lin_b = (const float*)d_in[5];
    const float* gamma = (const float*)d_in[6];
    const float* beta  = (const float*)d_in[7];
    float* out = (float*)d_out;

    int N = in_sizes[0] / DIM;
    int E = in_sizes[2];

    zero_kernel<<<2048, 256>>>();
    build_wcat<<<KTOT, DIM>>>(lin_w, relw);
    int warps = (E + 31) / 32;
    scatter_kernel<<<(warps + 7) / 8, 256>>>(x, ei, et, E);
    inv_kernel<<<(NNODES + 255) / 256, 256>>>();
    final_gemm_kernel<<<(N + BM - 1) / BM, 256>>>(x, lin_b, gamma, beta, out, N);
}